// round 6
// baseline (speedup 1.0000x reference)
#include <cuda_runtime.h>

#define NN 4
#define AA 8732
#define CC 81
#define TPB 256
#define NBLK ((AA + TPB - 1) / TPB)     /* 35 */

#define TPM 128                          /* k_main threads */
#define IT 4
#define ITILE (TPM * IT)                 /* 512 */
#define NBI 18                           /* ceil(8732/512) */
#define JCH 384                          /* 3 tiles of 128 */
#define SPLIT 24                         /* 24*384 = 9216 >= 8732 ; grid 1728 = 1 wave */

// ---------------- scratch (device globals: allocation-free) ----------------
__device__ float4 g_pbox[NN * AA];    // (l, t, r, b)
__device__ float4 g_gbox[NN * AA];
__device__ float  g_parea[NN * AA];
__device__ float  g_garea[NN * AA];
__device__ float  g_validf[NN * AA];
__device__ float  g_con[NN * AA];
__device__ float  g_conneg[NN * AA];
__device__ float  g_sl1[NN * AA];
__device__ int    g_posp[NN * NBLK];
__device__ int    g_pos[NN];
__device__ unsigned g_thr[NN];
__device__ float  g_ioup[SPLIT][NN * AA];
__device__ float  g_part1[NN * NBLK];
__device__ float  g_part2[NN * NBLK];

// ---------------- K1: per-anchor prep (no atomics; per-block pos partial) --
__global__ void __launch_bounds__(TPB) k_prep(
    const float* __restrict__ ploc, const float* __restrict__ plabel,
    const float* __restrict__ gloc, const int* __restrict__ glabel,
    const float* __restrict__ dbox)
{
    int n = blockIdx.y;
    int a = blockIdx.x * TPB + threadIdx.x;
    int ismask = 0;
    if (a < AA) {
        float dx = dbox[0 * AA + a], dy = dbox[1 * AA + a];
        float dw = dbox[2 * AA + a], dh = dbox[3 * AA + a];
        const float* pl = ploc + (size_t)n * 4 * AA;
        const float* gg = gloc + (size_t)n * 4 * AA;
        float px = pl[a], py = pl[AA + a], pw = pl[2 * AA + a], ph = pl[3 * AA + a];
        float gx = gg[a], gy = gg[AA + a], gw = gg[2 * AA + a], gh = gg[3 * AA + a];

        // encode targets (vec_gd) + smooth L1
        float gxt = 10.0f * (gx - dx) / dw;
        float gyt = 10.0f * (gy - dy) / dh;
        float gwt = 5.0f * __logf(gw / dw);
        float ght = 5.0f * __logf(gh / dh);

        float s = 0.f, d, ad;
        d = px - gxt; ad = fabsf(d); s += (ad < 1.f) ? 0.5f * d * d : ad - 0.5f;
        d = py - gyt; ad = fabsf(d); s += (ad < 1.f) ? 0.5f * d * d : ad - 0.5f;
        d = pw - gwt; ad = fabsf(d); s += (ad < 1.f) ? 0.5f * d * d : ad - 0.5f;
        d = ph - ght; ad = fabsf(d); s += (ad < 1.f) ? 0.5f * d * d : ad - 0.5f;

        // decode p -> ltrb
        float pcx = 0.1f * px * dw + dx, pcy = 0.1f * py * dh + dy;
        float pww = __expf(0.2f * pw) * dw, phh = __expf(0.2f * ph) * dh;
        float plx = pcx - 0.5f * pww, pty = pcy - 0.5f * phh;
        float prx = pcx + 0.5f * pww, pby = pcy + 0.5f * phh;
        // decode g -> ltrb
        float gcx = 0.1f * gx * dw + dx, gcy = 0.1f * gy * dh + dy;
        float gww = __expf(0.2f * gw) * dw, ghh = __expf(0.2f * gh) * dh;
        float glx = gcx - 0.5f * gww, gty = gcy - 0.5f * ghh;
        float grx = gcx + 0.5f * gww, gby = gcy + 0.5f * ghh;

        float pa = (prx - plx) * (pby - pty);
        float ga = (grx - glx) * (gby - gty);
        int valid = (plx < prx) && (pty < pby);

        // con = log(sum exp x) - x[label]   (inputs ~N(0,1): no max-shift)
        int lab = glabel[n * AA + a];
        const float* pp = plabel + (size_t)n * CC * AA + a;
        float se = 0.f;
        #pragma unroll 9
        for (int c = 0; c < CC; c++) se += __expf(pp[(size_t)c * AA]);
        float xg = pp[(size_t)lab * AA];
        float con = __logf(se) - xg;
        ismask = (lab > 0);

        int id = n * AA + a;
        g_pbox[id] = make_float4(plx, pty, prx, pby);
        g_gbox[id] = make_float4(glx, gty, grx, gby);
        g_parea[id] = pa;
        g_garea[id] = ga;
        g_validf[id] = valid ? 1.f : 0.f;
        g_con[id] = con;
        g_conneg[id] = ismask ? 0.f : con;
        g_sl1[id] = s;
    }
    __shared__ int wcnt[TPB / 32];
    unsigned bal = __ballot_sync(0xffffffffu, ismask);
    if ((threadIdx.x & 31) == 0) wcnt[threadIdx.x >> 5] = __popc(bal);
    __syncthreads();
    if (threadIdx.x == 0) {
        int sm = 0;
        #pragma unroll
        for (int w = 0; w < TPB / 32; w++) sm += wcnt[w];
        g_posp[n * NBLK + blockIdx.x] = sm;
    }
}

// ------- K2: exact K-th largest of con_neg (radix select on float bits) ----
__global__ void __launch_bounds__(1024) k_sel()
{
    int n = blockIdx.x;
    int t = threadIdx.x;
    int lane = t & 31;
    __shared__ int hist[256];
    __shared__ int suf[256];
    __shared__ int s_pos;
    __shared__ unsigned s_prefix;
    __shared__ int s_rem;

    if (t == 0) s_pos = 0;
    __syncthreads();
    if (t < 64) {
        int v = (t < NBLK) ? g_posp[n * NBLK + t] : 0;
        #pragma unroll
        for (int o = 16; o > 0; o >>= 1) v += __shfl_down_sync(0xffffffffu, v, o);
        if (lane == 0) atomicAdd(&s_pos, v);
    }
    __syncthreads();
    int pos = s_pos;
    if (t == 0) g_pos[n] = pos;
    int K = min(3 * pos, AA);
    if (K <= 0) { if (t == 0) g_thr[n] = 0xFFFFFFFFu; return; }
    if (t == 0) { s_prefix = 0; s_rem = K; }
    __syncthreads();

    for (int pass = 0; pass < 4; pass++) {
        int shift = 24 - 8 * pass;
        if (t < 256) hist[t] = 0;
        __syncthreads();
        unsigned pref = s_prefix;
        int rem = s_rem;
        for (int i = t; i < 9216; i += 1024) {
            bool ok = (i < AA);
            unsigned b = 0;
            if (ok) {
                b = __float_as_uint(g_conneg[n * AA + i]);
                if (pass > 0 && (b >> (shift + 8)) != pref) ok = false;
            }
            int bin = ok ? (int)((b >> shift) & 0xFF) : (256 + lane);
            unsigned mm = __match_any_sync(0xffffffffu, bin);
            if (ok && lane == (__ffs(mm) - 1)) atomicAdd(&hist[bin], __popc(mm));
        }
        __syncthreads();
        if (t < 256) suf[t] = hist[t];
        __syncthreads();
        // inclusive suffix sums (descending bins), Hillis-Steele
        for (int st = 1; st < 256; st <<= 1) {
            int v = 0;
            if (t < 256) v = suf[t] + ((t + st < 256) ? suf[t + st] : 0);
            __syncthreads();
            if (t < 256) suf[t] = v;
            __syncthreads();
        }
        if (t < 256) {
            int gt = (t < 255) ? suf[t + 1] : 0;   // strictly-greater-bin count
            if (suf[t] >= rem && gt < rem) {
                s_prefix = (pref << 8) | (unsigned)t;
                s_rem = rem - gt;
            }
        }
        __syncthreads();
    }
    if (t == 0) g_thr[n] = s_prefix;
}

// ------- K3: A x A IoU-sum, single-wave grid, 13 inst/pair ----------
__global__ void __launch_bounds__(TPM, 12) k_main()
{
    int n = blockIdx.z;
    int s = blockIdx.y;
    int t = threadIdx.x;
    int ibase = blockIdx.x * ITILE + t;

    __shared__ float4 sb[TPM];
    __shared__ float  sa[TPM];

    float4 pb[IT];
    float  pa[IT], acc[IT];

    #pragma unroll
    for (int k = 0; k < IT; k++) {
        int i = ibase + k * TPM;
        if (i < AA) {
            int id = n * AA + i;
            pb[k] = g_pbox[id];
            pa[k] = g_parea[id];
        } else {
            pb[k] = make_float4(-2e30f, -2e30f, -2e30f, -2e30f);
            pa[k] = 1.0f;
        }
        acc[k] = 0.f;
    }

    int j0 = s * JCH;
    int j1 = min(AA, j0 + JCH);

    for (int jb = j0; jb < j1; jb += TPM) {
        int j = jb + t;
        if (j < j1) {
            int jd = n * AA + j;
            sb[t] = g_gbox[jd];
            sa[t] = g_garea[jd];
        } else {
            sb[t] = make_float4(1e30f, 1e30f, 1e30f, 1e30f);
            sa[t] = 1.0f;
        }
        __syncthreads();

        #pragma unroll 8
        for (int u = 0; u < TPM; u++) {
            float4 gb = sb[u];
            float ga = sa[u];
            #pragma unroll
            for (int k = 0; k < IT; k++) {
                float x1 = fmaxf(pb[k].x, gb.x);
                float x2 = fminf(pb[k].z, gb.z);
                float y1 = fmaxf(pb[k].y, gb.y);
                float y2 = fminf(pb[k].w, gb.w);
                float iw = fmaxf(x2 - x1, 0.f);
                float ih = fmaxf(y2 - y1, 0.f);
                float inter = iw * ih;
                float ua = fmaf(inter, -1.0f, pa[k] + ga);
                float r;
                asm("rcp.approx.f32 %0, %1;" : "=f"(r) : "f"(ua));
                acc[k] = fmaf(inter, r, acc[k]);
            }
        }
        __syncthreads();
    }

    #pragma unroll
    for (int k = 0; k < IT; k++) {
        int i = ibase + k * TPM;
        if (i < AA) g_ioup[s][n * AA + i] = acc[k];
    }
}

// ------- K4: combine partials (fixed order), epilogue + block reduce -------
__global__ void __launch_bounds__(TPB) k_post(const int* __restrict__ glabel)
{
    int n = blockIdx.y;
    int i = blockIdx.x * TPB + threadIdx.x;
    int t = threadIdx.x;

    float a1 = 0.f, a2 = 0.f;
    if (i < AA) {
        int id = n * AA + i;
        float iou = 0.f;
        #pragma unroll
        for (int s = 0; s < SPLIT; s++) iou += g_ioup[s][id];

        float sl1 = g_sl1[id], con = g_con[id];
        float cn = g_conneg[id];
        float vld = g_validf[id];
        int lab = glabel[id];

        float w = (vld != 0.f) ? 0.01f * iou : 0.f;
        if (lab > 0) a1 = sl1 / (sl1 + w) * sl1;
        float nm = (__float_as_uint(cn) >= g_thr[n]) ? 1.f : 0.f;
        float mm = (lab > 0) ? 1.f : 0.f;
        a2 = con * (mm + nm);
    }

    __shared__ float r1[TPB];
    __shared__ float r2[TPB];
    r1[t] = a1; r2[t] = a2;
    __syncthreads();
    for (int sdim = TPB / 2; sdim > 0; sdim >>= 1) {
        if (t < sdim) { r1[t] += r1[t + sdim]; r2[t] += r2[t + sdim]; }
        __syncthreads();
    }
    if (t == 0) {
        g_part1[n * NBLK + blockIdx.x] = r1[0];
        g_part2[n * NBLK + blockIdx.x] = r2[0];
    }
}

// ---------------- K5: deterministic final reduce ----------------
__global__ void __launch_bounds__(128) k_final(float* __restrict__ out)
{
    int t = threadIdx.x, w = t >> 5, lane = t & 31;
    __shared__ float s_val[NN];
    if (w < NN) {
        float s1 = 0.f, s2 = 0.f;
        for (int b = lane; b < NBLK; b += 32) {
            s1 += g_part1[w * NBLK + b];
            s2 += g_part2[w * NBLK + b];
        }
        float v = s1 + s2;
        #pragma unroll
        for (int o = 16; o > 0; o >>= 1) v += __shfl_down_sync(0xffffffffu, v, o);
        if (lane == 0) {
            int pos = g_pos[w];
            s_val[w] = (pos > 0) ? v / fmaxf((float)pos, 1e-6f) : 0.f;
        }
    }
    __syncthreads();
    if (t == 0) out[0] = (s_val[0] + s_val[1] + s_val[2] + s_val[3]) * 0.25f;
}

// ---------------- launch ----------------
extern "C" void kernel_launch(void* const* d_in, const int* in_sizes, int n_in,
                              void* d_out, int out_size)
{
    const float* ploc   = (const float*)d_in[0];
    const float* plabel = (const float*)d_in[1];
    const float* gloc   = (const float*)d_in[2];
    const int*   glabel = (const int*)d_in[3];
    const float* dbox   = (const float*)d_in[4];
    float* out = (float*)d_out;

    k_prep<<<dim3(NBLK, NN), TPB>>>(ploc, plabel, gloc, glabel, dbox);
    k_sel<<<NN, 1024>>>();
    k_main<<<dim3(NBI, SPLIT, NN), TPM>>>();
    k_post<<<dim3(NBLK, NN), TPB>>>(glabel);
    k_final<<<1, 128>>>(out);
}

// round 7
// speedup vs baseline: 1.0781x; 1.0781x over previous
#include <cuda_runtime.h>

#define NN 4
#define AA 8732
#define CC 81
#define TPB 256
#define NBLK ((AA + TPB - 1) / TPB)     /* 35 */

#define TPM 64                           /* k_main threads */
#define IT 8
#define ITILE (TPM * IT)                 /* 512 */
#define NBI 18                           /* ceil(8732/512) */
#define JCH 256                          /* one shared tile per block */
#define SPLIT 35                         /* 35*256 = 8960 >= 8732 */

// ---------------- scratch (device globals: allocation-free) ----------------
__device__ float4 g_pbox[NN * AA];    // (l, t, r, b)
__device__ float4 g_gbox[NN * AA];
__device__ float  g_parea[NN * AA];
__device__ float  g_garea[NN * AA];
__device__ float  g_validf[NN * AA];
__device__ float  g_con[NN * AA];
__device__ float  g_conneg[NN * AA];
__device__ float  g_sl1[NN * AA];
__device__ int    g_posp[NN * NBLK];
__device__ int    g_pos[NN];
__device__ unsigned g_thr[NN];
__device__ float  g_ioup[SPLIT][NN * AA];
__device__ float  g_part1[NN * NBLK];
__device__ float  g_part2[NN * NBLK];

// ---------------- K1: per-anchor prep (no atomics; per-block pos partial) --
__global__ void __launch_bounds__(TPB) k_prep(
    const float* __restrict__ ploc, const float* __restrict__ plabel,
    const float* __restrict__ gloc, const int* __restrict__ glabel,
    const float* __restrict__ dbox)
{
    int n = blockIdx.y;
    int a = blockIdx.x * TPB + threadIdx.x;
    int ismask = 0;
    if (a < AA) {
        float dx = dbox[0 * AA + a], dy = dbox[1 * AA + a];
        float dw = dbox[2 * AA + a], dh = dbox[3 * AA + a];
        const float* pl = ploc + (size_t)n * 4 * AA;
        const float* gg = gloc + (size_t)n * 4 * AA;
        float px = pl[a], py = pl[AA + a], pw = pl[2 * AA + a], ph = pl[3 * AA + a];
        float gx = gg[a], gy = gg[AA + a], gw = gg[2 * AA + a], gh = gg[3 * AA + a];

        // encode targets (vec_gd) + smooth L1
        float gxt = 10.0f * (gx - dx) / dw;
        float gyt = 10.0f * (gy - dy) / dh;
        float gwt = 5.0f * __logf(gw / dw);
        float ght = 5.0f * __logf(gh / dh);

        float s = 0.f, d, ad;
        d = px - gxt; ad = fabsf(d); s += (ad < 1.f) ? 0.5f * d * d : ad - 0.5f;
        d = py - gyt; ad = fabsf(d); s += (ad < 1.f) ? 0.5f * d * d : ad - 0.5f;
        d = pw - gwt; ad = fabsf(d); s += (ad < 1.f) ? 0.5f * d * d : ad - 0.5f;
        d = ph - ght; ad = fabsf(d); s += (ad < 1.f) ? 0.5f * d * d : ad - 0.5f;

        // decode p -> ltrb
        float pcx = 0.1f * px * dw + dx, pcy = 0.1f * py * dh + dy;
        float pww = __expf(0.2f * pw) * dw, phh = __expf(0.2f * ph) * dh;
        float plx = pcx - 0.5f * pww, pty = pcy - 0.5f * phh;
        float prx = pcx + 0.5f * pww, pby = pcy + 0.5f * phh;
        // decode g -> ltrb
        float gcx = 0.1f * gx * dw + dx, gcy = 0.1f * gy * dh + dy;
        float gww = __expf(0.2f * gw) * dw, ghh = __expf(0.2f * gh) * dh;
        float glx = gcx - 0.5f * gww, gty = gcy - 0.5f * ghh;
        float grx = gcx + 0.5f * gww, gby = gcy + 0.5f * ghh;

        float pa = (prx - plx) * (pby - pty);
        float ga = (grx - glx) * (gby - gty);
        int valid = (plx < prx) && (pty < pby);

        // con = log(sum exp x) - x[label]   (inputs ~N(0,1): no max-shift)
        int lab = glabel[n * AA + a];
        const float* pp = plabel + (size_t)n * CC * AA + a;
        float se = 0.f;
        #pragma unroll 9
        for (int c = 0; c < CC; c++) se += __expf(pp[(size_t)c * AA]);
        float xg = pp[(size_t)lab * AA];
        float con = __logf(se) - xg;
        ismask = (lab > 0);

        int id = n * AA + a;
        g_pbox[id] = make_float4(plx, pty, prx, pby);
        g_gbox[id] = make_float4(glx, gty, grx, gby);
        g_parea[id] = pa;
        g_garea[id] = ga;
        g_validf[id] = valid ? 1.f : 0.f;
        g_con[id] = con;
        g_conneg[id] = ismask ? 0.f : con;
        g_sl1[id] = s;
    }
    __shared__ int wcnt[TPB / 32];
    unsigned bal = __ballot_sync(0xffffffffu, ismask);
    if ((threadIdx.x & 31) == 0) wcnt[threadIdx.x >> 5] = __popc(bal);
    __syncthreads();
    if (threadIdx.x == 0) {
        int sm = 0;
        #pragma unroll
        for (int w = 0; w < TPB / 32; w++) sm += wcnt[w];
        g_posp[n * NBLK + blockIdx.x] = sm;
    }
}

// ------- K2: exact K-th largest of con_neg (radix select on float bits) ----
__global__ void __launch_bounds__(1024) k_sel()
{
    int n = blockIdx.x;
    int t = threadIdx.x;
    int lane = t & 31;
    __shared__ int hist[256];
    __shared__ int suf[256];
    __shared__ int s_pos;
    __shared__ unsigned s_prefix;
    __shared__ int s_rem;

    if (t == 0) s_pos = 0;
    __syncthreads();
    if (t < 64) {
        int v = (t < NBLK) ? g_posp[n * NBLK + t] : 0;
        #pragma unroll
        for (int o = 16; o > 0; o >>= 1) v += __shfl_down_sync(0xffffffffu, v, o);
        if (lane == 0) atomicAdd(&s_pos, v);
    }
    __syncthreads();
    int pos = s_pos;
    if (t == 0) g_pos[n] = pos;
    int K = min(3 * pos, AA);
    if (K <= 0) { if (t == 0) g_thr[n] = 0xFFFFFFFFu; return; }
    if (t == 0) { s_prefix = 0; s_rem = K; }
    __syncthreads();

    for (int pass = 0; pass < 4; pass++) {
        int shift = 24 - 8 * pass;
        if (t < 256) hist[t] = 0;
        __syncthreads();
        unsigned pref = s_prefix;
        int rem = s_rem;
        for (int i = t; i < 9216; i += 1024) {
            bool ok = (i < AA);
            unsigned b = 0;
            if (ok) {
                b = __float_as_uint(g_conneg[n * AA + i]);
                if (pass > 0 && (b >> (shift + 8)) != pref) ok = false;
            }
            int bin = ok ? (int)((b >> shift) & 0xFF) : (256 + lane);
            unsigned mm = __match_any_sync(0xffffffffu, bin);
            if (ok && lane == (__ffs(mm) - 1)) atomicAdd(&hist[bin], __popc(mm));
        }
        __syncthreads();
        if (t < 256) suf[t] = hist[t];
        __syncthreads();
        // inclusive suffix sums (descending bins), Hillis-Steele
        for (int st = 1; st < 256; st <<= 1) {
            int v = 0;
            if (t < 256) v = suf[t] + ((t + st < 256) ? suf[t + st] : 0);
            __syncthreads();
            if (t < 256) suf[t] = v;
            __syncthreads();
        }
        if (t < 256) {
            int gt = (t < 255) ? suf[t + 1] : 0;   // strictly-greater-bin count
            if (suf[t] >= rem && gt < rem) {
                s_prefix = (pref << 8) | (unsigned)t;
                s_rem = rem - gt;
            }
        }
        __syncthreads();
    }
    if (t == 0) g_thr[n] = s_prefix;
}

// ------- K3: A x A IoU-sum; TPM=64, IT=8 for ILP; one tile per block -------
__global__ void __launch_bounds__(TPM) k_main()
{
    int n = blockIdx.z;
    int s = blockIdx.y;
    int t = threadIdx.x;
    int ibase = blockIdx.x * ITILE + t;

    __shared__ float4 sb[JCH];
    __shared__ float  sa[JCH];

    float4 pb[IT];
    float  pa[IT], acc[IT];

    #pragma unroll
    for (int k = 0; k < IT; k++) {
        int i = ibase + k * TPM;
        if (i < AA) {
            int id = n * AA + i;
            pb[k] = g_pbox[id];
            pa[k] = g_parea[id];
        } else {
            pb[k] = make_float4(-2e30f, -2e30f, -2e30f, -2e30f);
            pa[k] = 1.0f;
        }
        acc[k] = 0.f;
    }

    int j0 = s * JCH;
    int j1 = min(AA, j0 + JCH);
    int jn = j1 - j0;

    // load entire JCH tile once (pad with far-away boxes -> zero contribution)
    #pragma unroll
    for (int jj = t; jj < JCH; jj += TPM) {
        if (jj < jn) {
            int jd = n * AA + j0 + jj;
            sb[jj] = g_gbox[jd];
            sa[jj] = g_garea[jd];
        } else {
            sb[jj] = make_float4(1e30f, 1e30f, 1e30f, 1e30f);
            sa[jj] = 1.0f;
        }
    }
    __syncthreads();

    #pragma unroll 4
    for (int u = 0; u < JCH; u++) {
        float4 gb = sb[u];
        float ga = sa[u];
        #pragma unroll
        for (int k = 0; k < IT; k++) {
            float x1 = fmaxf(pb[k].x, gb.x);
            float x2 = fminf(pb[k].z, gb.z);
            float y1 = fmaxf(pb[k].y, gb.y);
            float y2 = fminf(pb[k].w, gb.w);
            float iw = fmaxf(x2 - x1, 0.f);
            float ih = fmaxf(y2 - y1, 0.f);
            float inter = iw * ih;
            float ua = fmaf(inter, -1.0f, pa[k] + ga);
            float r;
            asm("rcp.approx.f32 %0, %1;" : "=f"(r) : "f"(ua));
            acc[k] = fmaf(inter, r, acc[k]);
        }
    }

    #pragma unroll
    for (int k = 0; k < IT; k++) {
        int i = ibase + k * TPM;
        if (i < AA) g_ioup[s][n * AA + i] = acc[k];
    }
}

// ------- K4: combine partials (fixed order), epilogue + block reduce -------
__global__ void __launch_bounds__(TPB) k_post(const int* __restrict__ glabel)
{
    int n = blockIdx.y;
    int i = blockIdx.x * TPB + threadIdx.x;
    int t = threadIdx.x;

    float a1 = 0.f, a2 = 0.f;
    if (i < AA) {
        int id = n * AA + i;
        float iou = 0.f;
        #pragma unroll
        for (int s = 0; s < SPLIT; s++) iou += g_ioup[s][id];

        float sl1 = g_sl1[id], con = g_con[id];
        float cn = g_conneg[id];
        float vld = g_validf[id];
        int lab = glabel[id];

        float w = (vld != 0.f) ? 0.01f * iou : 0.f;
        if (lab > 0) a1 = sl1 / (sl1 + w) * sl1;
        float nm = (__float_as_uint(cn) >= g_thr[n]) ? 1.f : 0.f;
        float mm = (lab > 0) ? 1.f : 0.f;
        a2 = con * (mm + nm);
    }

    __shared__ float r1[TPB];
    __shared__ float r2[TPB];
    r1[t] = a1; r2[t] = a2;
    __syncthreads();
    for (int sdim = TPB / 2; sdim > 0; sdim >>= 1) {
        if (t < sdim) { r1[t] += r1[t + sdim]; r2[t] += r2[t + sdim]; }
        __syncthreads();
    }
    if (t == 0) {
        g_part1[n * NBLK + blockIdx.x] = r1[0];
        g_part2[n * NBLK + blockIdx.x] = r2[0];
    }
}

// ---------------- K5: deterministic final reduce ----------------
__global__ void __launch_bounds__(128) k_final(float* __restrict__ out)
{
    int t = threadIdx.x, w = t >> 5, lane = t & 31;
    __shared__ float s_val[NN];
    if (w < NN) {
        float s1 = 0.f, s2 = 0.f;
        for (int b = lane; b < NBLK; b += 32) {
            s1 += g_part1[w * NBLK + b];
            s2 += g_part2[w * NBLK + b];
        }
        float v = s1 + s2;
        #pragma unroll
        for (int o = 16; o > 0; o >>= 1) v += __shfl_down_sync(0xffffffffu, v, o);
        if (lane == 0) {
            int pos = g_pos[w];
            s_val[w] = (pos > 0) ? v / fmaxf((float)pos, 1e-6f) : 0.f;
        }
    }
    __syncthreads();
    if (t == 0) out[0] = (s_val[0] + s_val[1] + s_val[2] + s_val[3]) * 0.25f;
}

// ---------------- launch ----------------
extern "C" void kernel_launch(void* const* d_in, const int* in_sizes, int n_in,
                              void* d_out, int out_size)
{
    const float* ploc   = (const float*)d_in[0];
    const float* plabel = (const float*)d_in[1];
    const float* gloc   = (const float*)d_in[2];
    const int*   glabel = (const int*)d_in[3];
    const float* dbox   = (const float*)d_in[4];
    float* out = (float*)d_out;

    k_prep<<<dim3(NBLK, NN), TPB>>>(ploc, plabel, gloc, glabel, dbox);
    k_sel<<<NN, 1024>>>();
    k_main<<<dim3(NBI, SPLIT, NN), TPM>>>();
    k_post<<<dim3(NBLK, NN), TPB>>>(glabel);
    k_final<<<1, 128>>>(out);
}

// round 8
// speedup vs baseline: 1.2950x; 1.2012x over previous
#include <cuda_runtime.h>

#define NN 4
#define AA 8732
#define CC 81
#define TPB 256
#define NBLK ((AA + TPB - 1) / TPB)     /* 35 */

#define TPM 128                          /* k_main threads */
#define IT 4
#define ITILE (TPM * IT)                 /* 512 */
#define NBI 18                           /* ceil(8732/512) */
#define JCH 256
#define SPLIT 35                         /* 35*256 = 8960 >= 8732 */

// ---------------- scratch (device globals: allocation-free) ----------------
__device__ float4 g_pbox[NN * AA];    // (l, t, r, b)
__device__ float4 g_gbox[NN * AA];
__device__ float  g_parea[NN * AA];
__device__ float  g_garea[NN * AA];
__device__ float  g_validf[NN * AA];
__device__ float  g_con[NN * AA];
__device__ float  g_conneg[NN * AA];
__device__ float  g_sl1[NN * AA];
__device__ int    g_posp[NN * NBLK];
__device__ int    g_pos[NN];
__device__ unsigned g_thr[NN];
__device__ float  g_ioup[SPLIT][NN * AA];
__device__ float  g_part1[NN * NBLK];
__device__ float  g_part2[NN * NBLK];
__device__ int    g_done;               // zero-init; reset in-kernel each run

// ---------------- K1: per-anchor prep (no atomics; per-block pos partial) --
__global__ void __launch_bounds__(TPB) k_prep(
    const float* __restrict__ ploc, const float* __restrict__ plabel,
    const float* __restrict__ gloc, const int* __restrict__ glabel,
    const float* __restrict__ dbox)
{
    int n = blockIdx.y;
    int a = blockIdx.x * TPB + threadIdx.x;
    int ismask = 0;
    if (a < AA) {
        float dx = dbox[0 * AA + a], dy = dbox[1 * AA + a];
        float dw = dbox[2 * AA + a], dh = dbox[3 * AA + a];
        const float* pl = ploc + (size_t)n * 4 * AA;
        const float* gg = gloc + (size_t)n * 4 * AA;
        float px = pl[a], py = pl[AA + a], pw = pl[2 * AA + a], ph = pl[3 * AA + a];
        float gx = gg[a], gy = gg[AA + a], gw = gg[2 * AA + a], gh = gg[3 * AA + a];

        // encode targets (vec_gd) + smooth L1
        float gxt = 10.0f * (gx - dx) / dw;
        float gyt = 10.0f * (gy - dy) / dh;
        float gwt = 5.0f * __logf(gw / dw);
        float ght = 5.0f * __logf(gh / dh);

        float s = 0.f, d, ad;
        d = px - gxt; ad = fabsf(d); s += (ad < 1.f) ? 0.5f * d * d : ad - 0.5f;
        d = py - gyt; ad = fabsf(d); s += (ad < 1.f) ? 0.5f * d * d : ad - 0.5f;
        d = pw - gwt; ad = fabsf(d); s += (ad < 1.f) ? 0.5f * d * d : ad - 0.5f;
        d = ph - ght; ad = fabsf(d); s += (ad < 1.f) ? 0.5f * d * d : ad - 0.5f;

        // decode p -> ltrb
        float pcx = 0.1f * px * dw + dx, pcy = 0.1f * py * dh + dy;
        float pww = __expf(0.2f * pw) * dw, phh = __expf(0.2f * ph) * dh;
        float plx = pcx - 0.5f * pww, pty = pcy - 0.5f * phh;
        float prx = pcx + 0.5f * pww, pby = pcy + 0.5f * phh;
        // decode g -> ltrb
        float gcx = 0.1f * gx * dw + dx, gcy = 0.1f * gy * dh + dy;
        float gww = __expf(0.2f * gw) * dw, ghh = __expf(0.2f * gh) * dh;
        float glx = gcx - 0.5f * gww, gty = gcy - 0.5f * ghh;
        float grx = gcx + 0.5f * gww, gby = gcy + 0.5f * ghh;

        float pa = (prx - plx) * (pby - pty);
        float ga = (grx - glx) * (gby - gty);
        int valid = (plx < prx) && (pty < pby);

        // con = log(sum exp x) - x[label]   (inputs ~N(0,1): no max-shift)
        int lab = glabel[n * AA + a];
        const float* pp = plabel + (size_t)n * CC * AA + a;
        float se = 0.f;
        #pragma unroll 9
        for (int c = 0; c < CC; c++) se += __expf(pp[(size_t)c * AA]);
        float xg = pp[(size_t)lab * AA];
        float con = __logf(se) - xg;
        ismask = (lab > 0);

        int id = n * AA + a;
        g_pbox[id] = make_float4(plx, pty, prx, pby);
        g_gbox[id] = make_float4(glx, gty, grx, gby);
        g_parea[id] = pa;
        g_garea[id] = ga;
        g_validf[id] = valid ? 1.f : 0.f;
        g_con[id] = con;
        g_conneg[id] = ismask ? 0.f : con;
        g_sl1[id] = s;
    }
    __shared__ int wcnt[TPB / 32];
    unsigned bal = __ballot_sync(0xffffffffu, ismask);
    if ((threadIdx.x & 31) == 0) wcnt[threadIdx.x >> 5] = __popc(bal);
    __syncthreads();
    if (threadIdx.x == 0) {
        int sm = 0;
        #pragma unroll
        for (int w = 0; w < TPB / 32; w++) sm += wcnt[w];
        g_posp[n * NBLK + blockIdx.x] = sm;
    }
}

// ------- K2: A x A IoU-sum (champion config) + embedded radix-select -------
// grid (NBI+1, SPLIT, NN). Blocks with bx==NBI, by==0 run the exact K-th
// largest selection for batch bz (overlapped with the IoU wall); other
// bx==NBI blocks exit immediately.
__global__ void __launch_bounds__(TPM) k_main()
{
    int n = blockIdx.z;
    int s = blockIdx.y;
    int t = threadIdx.x;
    int bx = blockIdx.x;

    __shared__ float4 sb[TPM];
    __shared__ float  sa[TPM];

    if (bx == NBI) {
        if (s != 0) return;
        // ---- radix select: exact K-th largest of conneg bits ----
        __shared__ int s_hist[256];
        __shared__ int s_suf[256];
        __shared__ unsigned s_prefix;
        __shared__ int s_rem;
        if (t == 0) {
            int pos = 0;
            for (int b = 0; b < NBLK; b++) pos += g_posp[n * NBLK + b];
            g_pos[n] = pos;
            s_rem = min(3 * pos, AA);
            s_prefix = 0;
        }
        __syncthreads();
        if (s_rem <= 0) { if (t == 0) g_thr[n] = 0xFFFFFFFFu; return; }

        for (int pass = 0; pass < 4; pass++) {
            int shift = 24 - 8 * pass;
            #pragma unroll
            for (int b = t; b < 256; b += TPM) s_hist[b] = 0;
            __syncthreads();
            unsigned pref = s_prefix;
            int rem = s_rem;
            for (int i = t; i < 9216; i += TPM) {
                bool ok = (i < AA);
                unsigned bits = 0;
                if (ok) {
                    bits = __float_as_uint(g_conneg[n * AA + i]);
                    if (pass > 0 && (bits >> (shift + 8)) != pref) ok = false;
                }
                int bin = ok ? (int)((bits >> shift) & 0xFF) : (256 + (t & 31));
                unsigned mm = __match_any_sync(0xffffffffu, bin);
                if (ok && (t & 31) == (__ffs(mm) - 1)) atomicAdd(&s_hist[bin], __popc(mm));
            }
            __syncthreads();
            #pragma unroll
            for (int b = t; b < 256; b += TPM) s_suf[b] = s_hist[b];
            __syncthreads();
            // inclusive suffix sums (descending bins), Hillis-Steele, 2 cells/thread
            for (int st = 1; st < 256; st <<= 1) {
                int b0 = t, b1 = t + TPM;
                int v0 = s_suf[b0] + ((b0 + st < 256) ? s_suf[b0 + st] : 0);
                int v1 = s_suf[b1] + ((b1 + st < 256) ? s_suf[b1 + st] : 0);
                __syncthreads();
                s_suf[b0] = v0; s_suf[b1] = v1;
                __syncthreads();
            }
            #pragma unroll
            for (int b = t; b < 256; b += TPM) {
                int gt = (b < 255) ? s_suf[b + 1] : 0;
                if (s_suf[b] >= rem && gt < rem) {
                    s_prefix = (pref << 8) | (unsigned)b;
                    s_rem = rem - gt;
                }
            }
            __syncthreads();
        }
        if (t == 0) g_thr[n] = s_prefix;
        return;
    }

    // ---- IoU work (unchanged champion path) ----
    int ibase = bx * ITILE + t;

    float4 pb[IT];
    float  pa[IT], acc[IT];

    #pragma unroll
    for (int k = 0; k < IT; k++) {
        int i = ibase + k * TPM;
        if (i < AA) {
            int id = n * AA + i;
            pb[k] = g_pbox[id];
            pa[k] = g_parea[id];
        } else {
            pb[k] = make_float4(-2e30f, -2e30f, -2e30f, -2e30f);
            pa[k] = 1.0f;
        }
        acc[k] = 0.f;
    }

    int j0 = s * JCH;
    int j1 = min(AA, j0 + JCH);

    for (int jb = j0; jb < j1; jb += TPM) {
        int j = jb + t;
        if (j < j1) {
            int jd = n * AA + j;
            sb[t] = g_gbox[jd];
            sa[t] = g_garea[jd];
        } else {
            sb[t] = make_float4(1e30f, 1e30f, 1e30f, 1e30f);
            sa[t] = 1.0f;
        }
        __syncthreads();

        #pragma unroll 4
        for (int u = 0; u < TPM; u++) {
            float4 gb = sb[u];
            float ga = sa[u];
            #pragma unroll
            for (int k = 0; k < IT; k++) {
                float x1 = fmaxf(pb[k].x, gb.x);
                float x2 = fminf(pb[k].z, gb.z);
                float y1 = fmaxf(pb[k].y, gb.y);
                float y2 = fminf(pb[k].w, gb.w);
                float iw = fmaxf(x2 - x1, 0.f);
                float ih = fmaxf(y2 - y1, 0.f);
                float inter = iw * ih;
                float ua = fmaf(inter, -1.0f, pa[k] + ga);
                float r;
                asm("rcp.approx.f32 %0, %1;" : "=f"(r) : "f"(ua));
                acc[k] = fmaf(inter, r, acc[k]);
            }
        }
        __syncthreads();
    }

    #pragma unroll
    for (int k = 0; k < IT; k++) {
        int i = ibase + k * TPM;
        if (i < AA) g_ioup[s][n * AA + i] = acc[k];
    }
}

// ------- K3: combine partials, epilogue, block reduce, last-block final ----
__global__ void __launch_bounds__(TPB) k_post(const int* __restrict__ glabel,
                                              float* __restrict__ out)
{
    int n = blockIdx.y;
    int i = blockIdx.x * TPB + threadIdx.x;
    int t = threadIdx.x;

    float a1 = 0.f, a2 = 0.f;
    if (i < AA) {
        int id = n * AA + i;
        float iou = 0.f;
        #pragma unroll
        for (int s = 0; s < SPLIT; s++) iou += g_ioup[s][id];

        float sl1 = g_sl1[id], con = g_con[id];
        float cn = g_conneg[id];
        float vld = g_validf[id];
        int lab = glabel[id];

        float w = (vld != 0.f) ? 0.01f * iou : 0.f;
        if (lab > 0) a1 = sl1 / (sl1 + w) * sl1;
        float nm = (__float_as_uint(cn) >= g_thr[n]) ? 1.f : 0.f;
        float mm = (lab > 0) ? 1.f : 0.f;
        a2 = con * (mm + nm);
    }

    __shared__ float r1[TPB];
    __shared__ float r2[TPB];
    r1[t] = a1; r2[t] = a2;
    __syncthreads();
    for (int sdim = TPB / 2; sdim > 0; sdim >>= 1) {
        if (t < sdim) { r1[t] += r1[t + sdim]; r2[t] += r2[t + sdim]; }
        __syncthreads();
    }

    __shared__ int s_last;
    if (t == 0) {
        g_part1[n * NBLK + blockIdx.x] = r1[0];
        g_part2[n * NBLK + blockIdx.x] = r2[0];
        __threadfence();
        int prev = atomicAdd(&g_done, 1);
        s_last = (prev == NN * NBLK - 1) ? 1 : 0;
    }
    __syncthreads();

    if (s_last) {
        // deterministic final reduce: fixed-order sums per batch
        __shared__ float s_val[NN];
        int w = t >> 5, lane = t & 31;
        if (w < NN) {
            float s1 = 0.f, s2 = 0.f;
            for (int b = lane; b < NBLK; b += 32) {
                s1 += g_part1[w * NBLK + b];
                s2 += g_part2[w * NBLK + b];
            }
            float v = s1 + s2;
            #pragma unroll
            for (int o = 16; o > 0; o >>= 1) v += __shfl_down_sync(0xffffffffu, v, o);
            if (lane == 0) {
                int pos = g_pos[w];
                s_val[w] = (pos > 0) ? v / fmaxf((float)pos, 1e-6f) : 0.f;
            }
        }
        __syncthreads();
        if (t == 0) {
            out[0] = (s_val[0] + s_val[1] + s_val[2] + s_val[3]) * 0.25f;
            g_done = 0;   // reset for next graph replay
        }
    }
}

// ---------------- launch ----------------
extern "C" void kernel_launch(void* const* d_in, const int* in_sizes, int n_in,
                              void* d_out, int out_size)
{
    const float* ploc   = (const float*)d_in[0];
    const float* plabel = (const float*)d_in[1];
    const float* gloc   = (const float*)d_in[2];
    const int*   glabel = (const int*)d_in[3];
    const float* dbox   = (const float*)d_in[4];
    float* out = (float*)d_out;

    k_prep<<<dim3(NBLK, NN), TPB>>>(ploc, plabel, gloc, glabel, dbox);
    k_main<<<dim3(NBI + 1, SPLIT, NN), TPM>>>();
    k_post<<<dim3(NBLK, NN), TPB>>>(glabel, out);
}

// round 10
// speedup vs baseline: 5.0905x; 3.9308x over previous
#include <cuda_runtime.h>

#define NN 4
#define AA 8732
#define CC 81
#define TPB 256
#define NBLK ((AA + TPB - 1) / TPB)      /* 35: k_post blocks per batch */

#define APB 128                           /* anchors per k_prep block */
#define NBLK2 ((AA + APB - 1) / APB)      /* 69 */

#define MAXB 256                          /* slot-stride blocks per batch in k_iou */
#define TPI 256                           /* k_iou threads */

// ---------------- scratch (device globals: allocation-free) ----------------
__device__ float4 g_pbox[NN * AA];    // (l, t, r, b)
__device__ float4 g_gbox[NN * AA];
__device__ float  g_parea[NN * AA];
__device__ float  g_garea[NN * AA];
__device__ float  g_validf[NN * AA];
__device__ float  g_con[NN * AA];
__device__ float  g_conneg[NN * AA];
__device__ float  g_sl1[NN * AA];
__device__ float  g_iou[NN * AA];     // written only for positive anchors
__device__ int    g_plist[NN * AA];   // compacted positive anchor ids
__device__ int    g_cnt[NN];          // zero-init; reset by k_post each run
__device__ int    g_pos[NN];
__device__ unsigned g_thr[NN];
__device__ float  g_part1[NN * NBLK];
__device__ float  g_part2[NN * NBLK];
__device__ int    g_done;             // zero-init; reset by k_post each run

// ---------------- K1: per-anchor prep, class-split softmax + compaction ----
__global__ void __launch_bounds__(TPB) k_prep(
    const float* __restrict__ ploc, const float* __restrict__ plabel,
    const float* __restrict__ gloc, const int* __restrict__ glabel,
    const float* __restrict__ dbox)
{
    int n = blockIdx.y;
    int la = threadIdx.x & (APB - 1);
    int half = threadIdx.x >> 7;          // 0 or 1
    int a = blockIdx.x * APB + la;
    bool act = (a < AA);

    __shared__ float s_se[TPB];
    __shared__ float s_xg[APB];

    int lab = 0;
    float se = 0.f;
    if (act) {
        lab = glabel[n * AA + a];
        const float* pp = plabel + (size_t)n * CC * AA + a;
        int c0 = half ? 41 : 0;
        int c1 = half ? CC : 41;
        #pragma unroll 8
        for (int c = c0; c < c1; c++) se += __expf(pp[(size_t)c * AA]);
        // owner half writes x[label]
        if ((lab >= 41) == (half == 1)) s_xg[la] = pp[(size_t)lab * AA];
    }
    s_se[threadIdx.x] = se;
    __syncthreads();

    if (act && half == 0) {
        float con = __logf(s_se[la] + s_se[la + APB]) - s_xg[la];

        float dx = dbox[0 * AA + a], dy = dbox[1 * AA + a];
        float dw = dbox[2 * AA + a], dh = dbox[3 * AA + a];
        const float* pl = ploc + (size_t)n * 4 * AA;
        const float* gg = gloc + (size_t)n * 4 * AA;
        float px = pl[a], py = pl[AA + a], pw = pl[2 * AA + a], ph = pl[3 * AA + a];
        float gx = gg[a], gy = gg[AA + a], gw = gg[2 * AA + a], gh = gg[3 * AA + a];

        // encode targets (vec_gd) + smooth L1
        float gxt = 10.0f * (gx - dx) / dw;
        float gyt = 10.0f * (gy - dy) / dh;
        float gwt = 5.0f * __logf(gw / dw);
        float ght = 5.0f * __logf(gh / dh);

        float s = 0.f, d, ad;
        d = px - gxt; ad = fabsf(d); s += (ad < 1.f) ? 0.5f * d * d : ad - 0.5f;
        d = py - gyt; ad = fabsf(d); s += (ad < 1.f) ? 0.5f * d * d : ad - 0.5f;
        d = pw - gwt; ad = fabsf(d); s += (ad < 1.f) ? 0.5f * d * d : ad - 0.5f;
        d = ph - ght; ad = fabsf(d); s += (ad < 1.f) ? 0.5f * d * d : ad - 0.5f;

        // decode p -> ltrb
        float pcx = 0.1f * px * dw + dx, pcy = 0.1f * py * dh + dy;
        float pww = __expf(0.2f * pw) * dw, phh = __expf(0.2f * ph) * dh;
        float plx = pcx - 0.5f * pww, pty = pcy - 0.5f * phh;
        float prx = pcx + 0.5f * pww, pby = pcy + 0.5f * phh;
        // decode g -> ltrb
        float gcx = 0.1f * gx * dw + dx, gcy = 0.1f * gy * dh + dy;
        float gww = __expf(0.2f * gw) * dw, ghh = __expf(0.2f * gh) * dh;
        float glx = gcx - 0.5f * gww, gty = gcy - 0.5f * ghh;
        float grx = gcx + 0.5f * gww, gby = gcy + 0.5f * ghh;

        float pa = (prx - plx) * (pby - pty);
        float ga = (grx - glx) * (gby - gty);
        int valid = (plx < prx) && (pty < pby);

        int id = n * AA + a;
        g_pbox[id] = make_float4(plx, pty, prx, pby);
        g_gbox[id] = make_float4(glx, gty, grx, gby);
        g_parea[id] = pa;
        g_garea[id] = ga;
        g_validf[id] = valid ? 1.f : 0.f;
        g_con[id] = con;
        g_conneg[id] = (lab > 0) ? 0.f : con;
        g_sl1[id] = s;

        if (lab > 0) {
            int idx = atomicAdd(&g_cnt[n], 1);
            g_plist[n * AA + idx] = a;
        }
    }
}

// ------- K2: per-positive-anchor IoU sums + embedded radix select ----------
// grid (MAXB+1, NN). bx==MAXB: exact K-th largest of conneg (threshold).
// bx<MAXB: slot-stride over compacted positive anchors; one block per anchor,
// block-strided j loop over all 8732 g boxes, deterministic tree reduction.
__global__ void __launch_bounds__(TPI) k_iou()
{
    int n = blockIdx.y;
    int bx = blockIdx.x;
    int t = threadIdx.x;

    if (bx == MAXB) {
        // ---- radix select on float bits of conneg ----
        __shared__ int s_hist[256];
        __shared__ int s_suf[256];
        __shared__ unsigned s_prefix;
        __shared__ int s_rem;
        int pos = g_cnt[n];
        int K = min(3 * pos, AA);
        if (t == 0) { g_pos[n] = pos; s_prefix = 0; s_rem = K; }
        __syncthreads();
        if (K <= 0) { if (t == 0) g_thr[n] = 0xFFFFFFFFu; return; }

        for (int pass = 0; pass < 4; pass++) {
            int shift = 24 - 8 * pass;
            s_hist[t] = 0;
            __syncthreads();
            unsigned pref = s_prefix;
            int rem = s_rem;
            for (int i = t; i < 9216; i += TPI) {
                bool ok = (i < AA);
                unsigned bits = 0;
                if (ok) {
                    bits = __float_as_uint(g_conneg[n * AA + i]);
                    if (pass > 0 && (bits >> (shift + 8)) != pref) ok = false;
                }
                int bin = ok ? (int)((bits >> shift) & 0xFF) : (256 + (t & 31));
                unsigned mm = __match_any_sync(0xffffffffu, bin);
                if (ok && (t & 31) == (__ffs(mm) - 1)) atomicAdd(&s_hist[bin], __popc(mm));
            }
            __syncthreads();
            s_suf[t] = s_hist[t];
            __syncthreads();
            // inclusive suffix sums over descending bins (Hillis-Steele)
            for (int st = 1; st < 256; st <<= 1) {
                int v = s_suf[t] + ((t + st < 256) ? s_suf[t + st] : 0);
                __syncthreads();
                s_suf[t] = v;
                __syncthreads();
            }
            int gt = (t < 255) ? s_suf[t + 1] : 0;
            if (s_suf[t] >= rem && gt < rem) {
                s_prefix = (pref << 8) | (unsigned)t;
                s_rem = rem - gt;
            }
            __syncthreads();
        }
        if (t == 0) g_thr[n] = s_prefix;
        return;
    }

    int cnt = g_cnt[n];
    __shared__ float s_red[TPI];

    for (int slot = bx; slot < cnt; slot += MAXB) {
        int i = g_plist[n * AA + slot];
        float4 pb = g_pbox[n * AA + i];
        float pa = g_parea[n * AA + i];

        float acc[4] = {0.f, 0.f, 0.f, 0.f};
        #pragma unroll
        for (int u = 0; u < 35; u++) {       // 35*256 = 8960 >= 8732
            int j = t + u * TPI;
            if (j < AA) {
                float4 gb = g_gbox[n * AA + j];
                float ga = g_garea[n * AA + j];
                float x1 = fmaxf(pb.x, gb.x);
                float x2 = fminf(pb.z, gb.z);
                float y1 = fmaxf(pb.y, gb.y);
                float y2 = fminf(pb.w, gb.w);
                float iw = fmaxf(x2 - x1, 0.f);
                float ih = fmaxf(y2 - y1, 0.f);
                float inter = iw * ih;
                float ua = fmaf(inter, -1.0f, pa + ga);
                float r;
                asm("rcp.approx.f32 %0, %1;" : "=f"(r) : "f"(ua));
                acc[u & 3] = fmaf(inter, r, acc[u & 3]);
            }
        }
        s_red[t] = (acc[0] + acc[1]) + (acc[2] + acc[3]);
        __syncthreads();
        for (int sdim = TPI / 2; sdim > 0; sdim >>= 1) {
            if (t < sdim) s_red[t] += s_red[t + sdim];
            __syncthreads();
        }
        if (t == 0) g_iou[n * AA + i] = s_red[0];
        __syncthreads();
    }
}

// ------- K3: epilogue + block reduce + last-block deterministic final ------
__global__ void __launch_bounds__(TPB) k_post(const int* __restrict__ glabel,
                                              float* __restrict__ out)
{
    int n = blockIdx.y;
    int i = blockIdx.x * TPB + threadIdx.x;
    int t = threadIdx.x;

    float a1 = 0.f, a2 = 0.f;
    if (i < AA) {
        int id = n * AA + i;
        float con = g_con[id];
        float cn = g_conneg[id];
        int lab = glabel[id];

        if (lab > 0) {
            float sl1 = g_sl1[id];
            float vld = g_validf[id];
            float iou = g_iou[id];
            float w = (vld != 0.f) ? 0.01f * iou : 0.f;
            a1 = sl1 / (sl1 + w) * sl1;
        }
        float nm = (__float_as_uint(cn) >= g_thr[n]) ? 1.f : 0.f;
        float mm = (lab > 0) ? 1.f : 0.f;
        a2 = con * (mm + nm);
    }

    __shared__ float r1[TPB];
    __shared__ float r2[TPB];
    r1[t] = a1; r2[t] = a2;
    __syncthreads();
    for (int sdim = TPB / 2; sdim > 0; sdim >>= 1) {
        if (t < sdim) { r1[t] += r1[t + sdim]; r2[t] += r2[t + sdim]; }
        __syncthreads();
    }

    __shared__ int s_last;
    if (t == 0) {
        g_part1[n * NBLK + blockIdx.x] = r1[0];
        g_part2[n * NBLK + blockIdx.x] = r2[0];
        __threadfence();
        int prev = atomicAdd(&g_done, 1);
        s_last = (prev == NN * NBLK - 1) ? 1 : 0;
    }
    __syncthreads();

    if (s_last) {
        __shared__ float s_val[NN];
        int w = t >> 5, lane = t & 31;
        if (w < NN) {
            float s1 = 0.f, s2 = 0.f;
            for (int b = lane; b < NBLK; b += 32) {
                s1 += g_part1[w * NBLK + b];
                s2 += g_part2[w * NBLK + b];
            }
            float v = s1 + s2;
            #pragma unroll
            for (int o = 16; o > 0; o >>= 1) v += __shfl_down_sync(0xffffffffu, v, o);
            if (lane == 0) {
                int pos = g_pos[w];
                s_val[w] = (pos > 0) ? v / fmaxf((float)pos, 1e-6f) : 0.f;
            }
        }
        __syncthreads();
        if (t == 0) {
            out[0] = (s_val[0] + s_val[1] + s_val[2] + s_val[3]) * 0.25f;
            g_done = 0;                       // reset for next graph replay
            #pragma unroll
            for (int nn = 0; nn < NN; nn++) g_cnt[nn] = 0;
        }
    }
}

// ---------------- launch ----------------
extern "C" void kernel_launch(void* const* d_in, const int* in_sizes, int n_in,
                              void* d_out, int out_size)
{
    const float* ploc   = (const float*)d_in[0];
    const float* plabel = (const float*)d_in[1];
    const float* gloc   = (const float*)d_in[2];
    const int*   glabel = (const int*)d_in[3];
    const float* dbox   = (const float*)d_in[4];
    float* out = (float*)d_out;

    k_prep<<<dim3(NBLK2, NN), TPB>>>(ploc, plabel, gloc, glabel, dbox);
    k_iou<<<dim3(MAXB + 1, NN), TPI>>>();
    k_post<<<dim3(NBLK, NN), TPB>>>(glabel, out);
}